// round 1
// baseline (speedup 1.0000x reference)
#include <cuda_runtime.h>

// Problem constants
static constexpr int L   = 1024;   // h*w = 32*32
static constexpr int CIN = 256;    // channels
static constexpr int O3  = 6144;   // 3 * ATT
static constexpr int ATTD = 2048;  // HEADS * DH
static constexpr int NB  = 8;      // batch
static constexpr int NH  = 64;     // batch * heads

// Scratch (device globals: allocation-free rule)
__device__ float g_s  [(size_t)NB * O3 * L];     // QKV projections, 192 MiB
__device__ float g_att[(size_t)NH * L * L];      // attention matrices, 256 MiB
__device__ float g_o  [(size_t)NB * ATTD * L];   // attention output, 64 MiB
__device__ unsigned g_maxu[NH];
__device__ float    g_sum [NH];

__device__ __forceinline__ unsigned f2ord(float f) {
    unsigned u = __float_as_uint(f);
    return (u & 0x80000000u) ? ~u : (u | 0x80000000u);
}
__device__ __forceinline__ float ord2f(unsigned e) {
    unsigned u = (e & 0x80000000u) ? (e & 0x7FFFFFFFu) : ~e;
    return __uint_as_float(u);
}

__global__ void init_k() {
    int i = threadIdx.x;
    if (i < NH) { g_maxu[i] = 0u; g_sum[i] = 0.0f; }
}

// ---------------------------------------------------------------------------
// Tiled SGEMM: C[z] = A[z] (MxK or KxM if ATRANS) * B[z] (KxN), 128x128 tile,
// BK=8, 256 threads, 8x8 per thread. All dims divisible by tile sizes here.
// EPI: 1 = (acc + bias[row]) * scale      (QKV projection)
//      2 = raw write + global max atomics (attention scores)
//      3 = acc * (1 / g_sum[z])           (V @ P with softmax denominator)
//      4 = acc + bias[row]                (output projection)
// ---------------------------------------------------------------------------
template<bool ATRANS, int EPI>
__global__ __launch_bounds__(256) void gemm_k(
    const float* __restrict__ Ab, const float* __restrict__ Bb,
    float* __restrict__ Cb,
    int K, int lda, int ldb, int ldc,
    long sA, long sB, long sC,
    const float* __restrict__ bias, float scale)
{
    const float* A = Ab + (size_t)blockIdx.z * sA;
    const float* B = Bb + (size_t)blockIdx.z * sB;
    float* Cp      = Cb + (size_t)blockIdx.z * sC;
    const int m0 = blockIdx.y * 128;
    const int n0 = blockIdx.x * 128;

    __shared__ float As[8][128];
    __shared__ float Bs[8][128];

    const int tid = threadIdx.x;
    const int lr = tid >> 5;          // 0..7   (K rows for K-major loads)
    const int lc = (tid & 31) << 2;   // 0..124 (float4 columns)
    const int ar = tid >> 1;          // 0..127 (M rows, non-trans A load)
    const int ac = (tid & 1) << 2;    // 0 or 4

    const int tm = (tid >> 4) << 3;   // thread tile origin in M
    const int tn = (tid & 15) << 3;   // thread tile origin in N

    float acc[8][8];
    #pragma unroll
    for (int i = 0; i < 8; i++)
        #pragma unroll
        for (int j = 0; j < 8; j++) acc[i][j] = 0.0f;

    for (int k0 = 0; k0 < K; k0 += 8) {
        if (ATRANS) {
            // A is K x M (row-major, row length lda): same pattern as B
            float4 a4 = *(const float4*)(A + (size_t)(k0 + lr) * lda + m0 + lc);
            *(float4*)&As[lr][lc] = a4;
        } else {
            float4 a4 = *(const float4*)(A + (size_t)(m0 + ar) * lda + k0 + ac);
            As[ac + 0][ar] = a4.x;
            As[ac + 1][ar] = a4.y;
            As[ac + 2][ar] = a4.z;
            As[ac + 3][ar] = a4.w;
        }
        float4 b4 = *(const float4*)(B + (size_t)(k0 + lr) * ldb + n0 + lc);
        *(float4*)&Bs[lr][lc] = b4;
        __syncthreads();

        #pragma unroll
        for (int kk = 0; kk < 8; kk++) {
            float a[8], b[8];
            #pragma unroll
            for (int i = 0; i < 8; i++) a[i] = As[kk][tm + i];
            #pragma unroll
            for (int j = 0; j < 8; j++) b[j] = Bs[kk][tn + j];
            #pragma unroll
            for (int i = 0; i < 8; i++)
                #pragma unroll
                for (int j = 0; j < 8; j++)
                    acc[i][j] += a[i] * b[j];
        }
        __syncthreads();
    }

    float inv = 1.0f;
    if (EPI == 3) inv = 1.0f / g_sum[blockIdx.z];

    float lm = -3.402823e38f;
    #pragma unroll
    for (int i = 0; i < 8; i++) {
        float bb = 0.0f;
        if (EPI == 1 || EPI == 4) bb = bias[m0 + tm + i];
        float* crow = Cp + (size_t)(m0 + tm + i) * ldc + n0 + tn;
        #pragma unroll
        for (int j = 0; j < 8; j += 4) {
            float v0 = acc[i][j + 0], v1 = acc[i][j + 1];
            float v2 = acc[i][j + 2], v3 = acc[i][j + 3];
            if (EPI == 1) {
                v0 = (v0 + bb) * scale; v1 = (v1 + bb) * scale;
                v2 = (v2 + bb) * scale; v3 = (v3 + bb) * scale;
            } else if (EPI == 4) {
                v0 += bb; v1 += bb; v2 += bb; v3 += bb;
            } else if (EPI == 3) {
                v0 *= inv; v1 *= inv; v2 *= inv; v3 *= inv;
            } else if (EPI == 2) {
                lm = fmaxf(lm, fmaxf(fmaxf(v0, v1), fmaxf(v2, v3)));
            }
            *(float4*)(crow + j) = make_float4(v0, v1, v2, v3);
        }
    }

    if (EPI == 2) {
        __shared__ unsigned smax;
        if (tid == 0) smax = 0u;
        __syncthreads();
        atomicMax(&smax, f2ord(lm));
        __syncthreads();
        if (tid == 0) atomicMax(&g_maxu[blockIdx.z], smax);
    }
}

// Global softmax middle pass: p = exp(att - max), accumulate per-(n,h) sum.
__global__ __launch_bounds__(256) void exp_sum_k() {
    const int z = blockIdx.y;
    const float m = ord2f(g_maxu[z]);
    float4* p = (float4*)(g_att + (size_t)z * L * L);
    const int total = L * L / 4;   // 262144 float4s

    float lsum = 0.0f;
    for (int i = blockIdx.x * blockDim.x + threadIdx.x; i < total;
         i += gridDim.x * blockDim.x) {
        float4 v = p[i];
        v.x = __expf(v.x - m);
        v.y = __expf(v.y - m);
        v.z = __expf(v.z - m);
        v.w = __expf(v.w - m);
        p[i] = v;
        lsum += v.x + v.y + v.z + v.w;
    }

    __shared__ float sd[256];
    sd[threadIdx.x] = lsum;
    __syncthreads();
    for (int s = 128; s > 0; s >>= 1) {
        if (threadIdx.x < s) sd[threadIdx.x] += sd[threadIdx.x + s];
        __syncthreads();
    }
    if (threadIdx.x == 0) atomicAdd(&g_sum[z], sd[0]);
}

extern "C" void kernel_launch(void* const* d_in, const int* in_sizes, int n_in,
                              void* d_out, int out_size)
{
    // Identify inputs by unique element counts (robust to ordering)
    const float *x = nullptr, *w_in = nullptr, *b_in = nullptr;
    const float *w_out = nullptr, *b_out = nullptr;
    for (int i = 0; i < n_in; i++) {
        const float* p = (const float*)d_in[i];
        switch (in_sizes[i]) {
            case NB * CIN * L:   x     = p; break;  // 2097152
            case O3 * CIN:       w_in  = p; break;  // 1572864
            case O3:             b_in  = p; break;  // 6144
            case CIN * ATTD:     w_out = p; break;  // 524288
            case CIN:            b_out = p; break;  // 256
            default: break;
        }
    }
    float* out = (float*)d_out;

    void *ps, *pa, *po;
    cudaGetSymbolAddress(&ps, g_s);
    cudaGetSymbolAddress(&pa, g_att);
    cudaGetSymbolAddress(&po, g_o);
    float* S = (float*)ps;
    float* P = (float*)pa;
    float* O = (float*)po;

    // SCALE = 1/sqrt(256) / sqrt(2/6400) * sqrt(2/2304) = (1/16)*(80/48) = 5/48
    const float SC = 5.0f / 48.0f;

    init_k<<<1, 64>>>();

    // K1: S[n] (6144x1024) = w_in (6144x256) @ x[n] (256x1024); epi (+bias)*SCALE
    gemm_k<false, 1><<<dim3(L / 128, O3 / 128, NB), 256>>>(
        w_in, x, S, CIN, CIN, L, L,
        0L, (long)CIN * L, (long)O3 * L, b_in, SC);

    // K2: att[z] (1024x1024) = q^T k, q = S[z*768K..], k = q + 256*L; epi raw + max
    gemm_k<true, 2><<<dim3(8, 8, NH), 256>>>(
        S, S + (size_t)256 * L, P, 256, L, L, L,
        (long)768 * L, (long)768 * L, (long)L * L, nullptr, 1.0f);

    // K3: global softmax exp + sum per (n,h)
    exp_sum_k<<<dim3(256, NH), 256>>>();

    // K4: o[z] (256x1024) = v (256x1024) @ p (1024x1024); epi * 1/sum[z]
    gemm_k<false, 3><<<dim3(8, 2, NH), 256>>>(
        S + (size_t)512 * L, P, O, L, L, L, L,
        (long)768 * L, (long)L * L, (long)256 * L, nullptr, 1.0f);

    // K5: out[n] (256x1024) = w_out (256x2048) @ o[n] (2048x1024) + b_out
    gemm_k<false, 4><<<dim3(8, 2, NB), 256>>>(
        w_out, O, out, ATTD, ATTD, L, L,
        0L, (long)ATTD * L, (long)CIN * L, b_out, 1.0f);
}

// round 3
// speedup vs baseline: 2.6436x; 2.6436x over previous
#include <cuda_runtime.h>
#include <cstdint>

static constexpr int L = 1024, CIN = 256, O3 = 6144, ATTD = 2048, NB = 8, NH = 64;
static constexpr float SC = 5.0f / 48.0f;   // exact closed form of SCALE
static constexpr unsigned SMEM_BYTES = 2 * (16384 + 16384);  // 2 stages x (A+B)

// Scratch (device globals per allocation-free rule)
__device__ float g_xt[(size_t)NB * L * CIN];    //   8 MB  x transposed [n][l][c]
__device__ float g_st[(size_t)NB * L * O3];     // 192 MB  S_T [n][l][o] (q,k slices used)
__device__ float g_v [(size_t)NB * ATTD * L];   //  64 MB  V  [n][a][l]
__device__ float g_p [(size_t)NH * L * L];      // 256 MB  Pm [z][m][l] = exp(att^T)
__device__ float g_ot[(size_t)NB * L * ATTD];   //  64 MB  O_T [n][m][a]
__device__ float g_sum[NH];

// ---------------------------------------------------------------------------
__device__ __forceinline__ unsigned s2u(const void* p) {
    unsigned a;
    asm("{ .reg .u64 t; cvta.to.shared.u64 t, %1; cvt.u32.u64 %0, t; }"
        : "=r"(a) : "l"(p));
    return a;
}
__device__ __forceinline__ float ldsf(unsigned a) {
    float v;
    asm volatile("ld.shared.f32 %0, [%1];" : "=f"(v) : "r"(a));
    return v;
}
__device__ __forceinline__ unsigned tf32(float f) {
    unsigned u;
    asm("cvt.rna.tf32.f32 %0, %1;" : "=r"(u) : "f"(f));
    return u;
}
__device__ __forceinline__ void mma8(float* d, const unsigned* a, const unsigned* b) {
    asm volatile(
        "mma.sync.aligned.m16n8k8.row.col.f32.tf32.tf32.f32 "
        "{%0,%1,%2,%3}, {%4,%5,%6,%7}, {%8,%9}, {%0,%1,%2,%3};"
        : "+f"(d[0]), "+f"(d[1]), "+f"(d[2]), "+f"(d[3])
        : "r"(a[0]), "r"(a[1]), "r"(a[2]), "r"(a[3]), "r"(b[0]), "r"(b[1]));
}
#define CPA16(dst, src) \
    asm volatile("cp.async.cg.shared.global [%0], [%1], 16;" :: "r"(dst), "l"(src) : "memory")

__global__ void init_k() {
    if (threadIdx.x < NH) g_sum[threadIdx.x] = 0.0f;
}

// x[n][c][l] -> xt[n][l][c]
__global__ __launch_bounds__(256) void transpose_k(const float* __restrict__ x,
                                                   float* __restrict__ xt) {
    __shared__ float t[32][33];
    const int n = blockIdx.z, c0 = blockIdx.y * 32, l0 = blockIdx.x * 32;
    const int tx = threadIdx.x, ty = threadIdx.y;
    const float* xp = x + ((size_t)n * CIN + c0) * L + l0;
    #pragma unroll
    for (int i = 0; i < 4; i++) t[ty + i * 8][tx] = xp[(size_t)(ty + i * 8) * L + tx];
    __syncthreads();
    float* xo = xt + ((size_t)n * L + l0) * CIN + c0;
    #pragma unroll
    for (int i = 0; i < 4; i++) xo[(size_t)(ty + i * 8) * CIN + tx] = t[tx][ty + i * 8];
}

// ---------------------------------------------------------------------------
// tf32 mma.sync GEMM: C[128x128] = A[128xK] * B[128xK]^T (both K-major).
// CTA 128x128x32, 8 warps (2x4), warp tile 64x32, mma m16n8k8.
// ID 0: S_T(q,k) = XT * w_in^T,  epi (acc + b_in[col]) * SC
// ID 1: V        = w_in * XT^T,  epi (acc + b_in[row]) * SC
// ID 2: Pm       = K_T * Q_T^T,  epi exp(acc), per-head sum -> g_sum
// ID 3: O_T      = Pm * V^T,     epi acc / g_sum[z]
// ID 4: out      = w_out * O_T^T,epi acc + b_out[row]
// ---------------------------------------------------------------------------
template<int ID>
__global__ __launch_bounds__(256) void gemm_tc(
    const float* __restrict__ A0, const float* __restrict__ B0,
    float* __restrict__ C0, const float* __restrict__ bias)
{
    extern __shared__ float smemf[];
    const unsigned sb = s2u(smemf);
    const int tid = threadIdx.x, wid = tid >> 5, lid = tid & 31;
    const int gid = lid >> 2, tig = lid & 3;
    const int wm = wid & 1, wn = wid >> 1;          // warp grid 2 x 4
    const int bx = blockIdx.x, by = blockIdx.y, z = blockIdx.z;

    const float *A, *B;
    float* C;
    int lda, ldb, ldc, K;
    const float* biN = nullptr;
    const float* biM = nullptr;

    if constexpr (ID == 0) {
        const int o0 = (bx >> 2) * 768 + (bx & 3) * 128;
        A = A0 + (size_t)z * L * CIN + (size_t)by * 128 * CIN; lda = CIN;
        B = B0 + (size_t)o0 * CIN; ldb = CIN;
        C = C0 + (size_t)z * L * O3 + (size_t)by * 128 * O3 + o0; ldc = O3;
        biN = bias + o0; K = CIN;
    } else if constexpr (ID == 1) {
        const int o0 = (by >> 1) * 768 + 512 + (by & 1) * 128;
        A = A0 + (size_t)o0 * CIN; lda = CIN;
        B = B0 + (size_t)z * L * CIN + (size_t)bx * 128 * CIN; ldb = CIN;
        C = C0 + (size_t)z * ATTD * L +
            (size_t)((by >> 1) * 256 + (by & 1) * 128) * L + bx * 128; ldc = L;
        biM = bias + o0; K = CIN;
    } else if constexpr (ID == 2) {
        const float* base = A0 + (size_t)(z >> 3) * L * O3 + (z & 7) * 768;
        A = base + 256 + (size_t)by * 128 * O3; lda = O3;   // keys (m)
        B = base + (size_t)bx * 128 * O3; ldb = O3;         // queries (l)
        C = C0 + (size_t)z * L * L + (size_t)by * 128 * L + bx * 128; ldc = L;
        K = CIN;
    } else if constexpr (ID == 3) {
        A = A0 + (size_t)z * L * L + (size_t)by * 128 * L; lda = L;
        B = B0 + (size_t)(z >> 3) * ATTD * L +
            (size_t)((z & 7) * 256 + bx * 128) * L; ldb = L;
        C = C0 + (size_t)(z >> 3) * L * ATTD + (size_t)by * 128 * ATTD +
            (z & 7) * 256 + bx * 128; ldc = ATTD;
        K = L;
    } else {
        A = A0 + (size_t)by * 128 * ATTD; lda = ATTD;
        B = B0 + (size_t)z * L * ATTD + (size_t)bx * 128 * ATTD; ldb = ATTD;
        C = C0 + (size_t)z * CIN * L + (size_t)by * 128 * L + bx * 128; ldc = L;
        biM = bias + by * 128; K = ATTD;
    }

    float acc[4][4][4];
    #pragma unroll
    for (int mt = 0; mt < 4; mt++)
        #pragma unroll
        for (int nt = 0; nt < 4; nt++)
            #pragma unroll
            for (int r = 0; r < 4; r++) acc[mt][nt][r] = 0.0f;

    // Tile loader: 128 rows x 32 floats, XOR-swizzled at 16B granularity
    auto load_chunk = [&](int kc, int buf) {
        const float* ak = A + kc * 32;
        const float* bk = B + kc * 32;
        const unsigned sA = sb + buf * 32768u;
        const unsigned sB = sA + 16384u;
        #pragma unroll
        for (int i = 0; i < 4; i++) {
            const int idx = tid + i * 256, r = idx >> 3, c4 = idx & 7;
            const unsigned so = (unsigned)(r * 128 + ((c4 ^ (r & 7)) << 4));
            CPA16(sA + so, ak + (size_t)r * lda + c4 * 4);
        }
        #pragma unroll
        for (int i = 0; i < 4; i++) {
            const int idx = tid + i * 256, r = idx >> 3, c4 = idx & 7;
            const unsigned so = (unsigned)(r * 128 + ((c4 ^ (r & 7)) << 4));
            CPA16(sB + so, bk + (size_t)r * ldb + c4 * 4);
        }
        asm volatile("cp.async.commit_group;" ::: "memory");
    };

    const int NC = K >> 5;
    load_chunk(0, 0);

    for (int c = 0; c < NC; c++) {
        const int buf = c & 1;
        if (c + 1 < NC) {
            load_chunk(c + 1, buf ^ 1);
            asm volatile("cp.async.wait_group 1;" ::: "memory");
        } else {
            asm volatile("cp.async.wait_group 0;" ::: "memory");
        }
        __syncthreads();

        const unsigned sA = sb + buf * 32768u;
        const unsigned sB = sA + 16384u;
        unsigned aRB[4], bRB[4];
        #pragma unroll
        for (int mt = 0; mt < 4; mt++)
            aRB[mt] = sA + (unsigned)((wm * 64 + mt * 16 + gid) * 128);
        #pragma unroll
        for (int nt = 0; nt < 4; nt++)
            bRB[nt] = sB + (unsigned)((wn * 32 + nt * 8 + gid) * 128);

        #pragma unroll
        for (int ks = 0; ks < 4; ks++) {
            const unsigned o0 = (unsigned)((((2 * ks) ^ gid) << 4) + tig * 4);
            const unsigned o1 = (unsigned)((((2 * ks + 1) ^ gid) << 4) + tig * 4);
            unsigned af[4][4], bf[4][2];
            #pragma unroll
            for (int mt = 0; mt < 4; mt++) {
                af[mt][0] = tf32(ldsf(aRB[mt] + o0));
                af[mt][1] = tf32(ldsf(aRB[mt] + 1024u + o0));
                af[mt][2] = tf32(ldsf(aRB[mt] + o1));
                af[mt][3] = tf32(ldsf(aRB[mt] + 1024u + o1));
            }
            #pragma unroll
            for (int nt = 0; nt < 4; nt++) {
                bf[nt][0] = tf32(ldsf(bRB[nt] + o0));
                bf[nt][1] = tf32(ldsf(bRB[nt] + o1));
            }
            #pragma unroll
            for (int mt = 0; mt < 4; mt++)
                #pragma unroll
                for (int nt = 0; nt < 4; nt++)
                    mma8(acc[mt][nt], af[mt], bf[nt]);
        }
        __syncthreads();
    }

    // Epilogue. Thread owns rows wm*64+mt*16+gid(+8), cols wn*32+nt*8+tig*2(+1)
    float vinv = 1.0f, lsum = 0.0f;
    if constexpr (ID == 3) vinv = 1.0f / g_sum[z];

    #pragma unroll
    for (int mt = 0; mt < 4; mt++) {
        const int r0 = wm * 64 + mt * 16 + gid;
        float bm0 = 0.0f, bm1 = 0.0f;
        if constexpr (ID == 1 || ID == 4) { bm0 = biM[r0]; bm1 = biM[r0 + 8]; }
        #pragma unroll
        for (int nt = 0; nt < 4; nt++) {
            const int cn = wn * 32 + nt * 8 + tig * 2;
            float v0 = acc[mt][nt][0], v1 = acc[mt][nt][1];
            float v2 = acc[mt][nt][2], v3 = acc[mt][nt][3];
            if constexpr (ID == 0) {
                const float2 bv = *(const float2*)(biN + cn);
                v0 = (v0 + bv.x) * SC; v1 = (v1 + bv.y) * SC;
                v2 = (v2 + bv.x) * SC; v3 = (v3 + bv.y) * SC;
            } else if constexpr (ID == 1) {
                v0 = (v0 + bm0) * SC; v1 = (v1 + bm0) * SC;
                v2 = (v2 + bm1) * SC; v3 = (v3 + bm1) * SC;
            } else if constexpr (ID == 2) {
                v0 = __expf(v0); v1 = __expf(v1);
                v2 = __expf(v2); v3 = __expf(v3);
                lsum += (v0 + v1) + (v2 + v3);
            } else if constexpr (ID == 3) {
                v0 *= vinv; v1 *= vinv; v2 *= vinv; v3 *= vinv;
            } else {
                v0 += bm0; v1 += bm0; v2 += bm1; v3 += bm1;
            }
            *(float2*)(C + (size_t)r0 * ldc + cn)       = make_float2(v0, v1);
            *(float2*)(C + (size_t)(r0 + 8) * ldc + cn) = make_float2(v2, v3);
        }
    }

    if constexpr (ID == 2) {
        __syncthreads();
        smemf[tid] = lsum;
        __syncthreads();
        for (int s = 128; s > 0; s >>= 1) {
            if (tid < s) smemf[tid] += smemf[tid + s];
            __syncthreads();
        }
        if (tid == 0) atomicAdd(&g_sum[z], smemf[0]);
    }
}

// ---------------------------------------------------------------------------
extern "C" void kernel_launch(void* const* d_in, const int* in_sizes, int n_in,
                              void* d_out, int out_size)
{
    const float *x = nullptr, *w_in = nullptr, *b_in = nullptr;
    const float *w_out = nullptr, *b_out = nullptr;
    for (int i = 0; i < n_in; i++) {
        const float* p = (const float*)d_in[i];
        switch (in_sizes[i]) {
            case NB * CIN * L:  x     = p; break;
            case O3 * CIN:      w_in  = p; break;
            case O3:            b_in  = p; break;
            case CIN * ATTD:    w_out = p; break;
            case CIN:           b_out = p; break;
            default: break;
        }
    }
    float* out = (float*)d_out;

    void* p;
    cudaGetSymbolAddress(&p, g_xt); float* XT = (float*)p;
    cudaGetSymbolAddress(&p, g_st); float* ST = (float*)p;
    cudaGetSymbolAddress(&p, g_v);  float* V  = (float*)p;
    cudaGetSymbolAddress(&p, g_p);  float* P  = (float*)p;
    cudaGetSymbolAddress(&p, g_ot); float* OT = (float*)p;

    cudaFuncSetAttribute(gemm_tc<0>, cudaFuncAttributeMaxDynamicSharedMemorySize, SMEM_BYTES);
    cudaFuncSetAttribute(gemm_tc<1>, cudaFuncAttributeMaxDynamicSharedMemorySize, SMEM_BYTES);
    cudaFuncSetAttribute(gemm_tc<2>, cudaFuncAttributeMaxDynamicSharedMemorySize, SMEM_BYTES);
    cudaFuncSetAttribute(gemm_tc<3>, cudaFuncAttributeMaxDynamicSharedMemorySize, SMEM_BYTES);
    cudaFuncSetAttribute(gemm_tc<4>, cudaFuncAttributeMaxDynamicSharedMemorySize, SMEM_BYTES);

    init_k<<<1, 64>>>();
    transpose_k<<<dim3(32, 8, 8), dim3(32, 8)>>>(x, XT);
    // K1a: S_T (q,k): N-tiles = 8 heads x 4 (512 cols), M-tiles = 8, z = batch
    gemm_tc<0><<<dim3(32, 8, 8), 128 * 2, SMEM_BYTES>>>(XT, w_in, ST, b_in);
    // K1b: V: N-tiles = 8 (L), M-tiles = 16 (8 heads x 256 rows), z = batch
    gemm_tc<1><<<dim3(8, 16, 8), 128 * 2, SMEM_BYTES>>>(w_in, XT, V, b_in);
    // K2: Pm = exp(K_T Q_T^T), per-head sums
    gemm_tc<2><<<dim3(8, 8, 64), 128 * 2, SMEM_BYTES>>>(ST, ST, P, nullptr);
    // K4: O_T = (Pm V^T) / sum
    gemm_tc<3><<<dim3(2, 8, 64), 128 * 2, SMEM_BYTES>>>(P, V, OT, nullptr);
    // K5: out = w_out O_T^T + b_out
    gemm_tc<4><<<dim3(8, 2, 8), 128 * 2, SMEM_BYTES>>>(w_out, OT, out, b_out);
}

// round 4
// speedup vs baseline: 2.9616x; 1.1203x over previous
#include <cuda_runtime.h>
#include <cstdint>

static constexpr int L = 1024, CIN = 256, O3 = 6144, ATTD = 2048, NB = 8, NH = 64;
static constexpr float SC = 5.0f / 48.0f;
static constexpr unsigned SMEM_BYTES = 2 * (16384 + 16384);

// Scratch (device globals per allocation-free rule)
__device__ float g_xt[(size_t)NB * L * CIN];
__device__ float g_st[(size_t)NB * L * O3];
__device__ float g_v [(size_t)NB * ATTD * L];
__device__ float g_p [(size_t)NH * L * L];
__device__ float g_ot[(size_t)NB * L * ATTD];
__device__ float g_win[(size_t)O3 * CIN];
__device__ float g_wout[(size_t)CIN * ATTD];
__device__ float g_sum[NH];

// ---------------------------------------------------------------------------
__device__ __forceinline__ unsigned s2u(const void* p) {
    unsigned a;
    asm("{ .reg .u64 t; cvta.to.shared.u64 t, %1; cvt.u32.u64 %0, t; }"
        : "=r"(a) : "l"(p));
    return a;
}
__device__ __forceinline__ float tf32r(float f) {   // round-to-tf32, as float
    unsigned u;
    asm("cvt.rna.tf32.f32 %0, %1;" : "=r"(u) : "f"(f));
    return __uint_as_float(u);
}
__device__ __forceinline__ void mma8(float* d, const unsigned* a, const unsigned* b) {
    asm volatile(
        "mma.sync.aligned.m16n8k8.row.col.f32.tf32.tf32.f32 "
        "{%0,%1,%2,%3}, {%4,%5,%6,%7}, {%8,%9}, {%0,%1,%2,%3};"
        : "+f"(d[0]), "+f"(d[1]), "+f"(d[2]), "+f"(d[3])
        : "r"(a[0]), "r"(a[1]), "r"(a[2]), "r"(a[3]), "r"(b[0]), "r"(b[1]));
}
#define LDSM4(r, addr) \
    asm volatile("ldmatrix.sync.aligned.m8n8.x4.shared.b16 {%0,%1,%2,%3}, [%4];" \
                 : "=r"((r)[0]), "=r"((r)[1]), "=r"((r)[2]), "=r"((r)[3]) : "r"(addr))
#define LDSM2(r, addr) \
    asm volatile("ldmatrix.sync.aligned.m8n8.x2.shared.b16 {%0,%1}, [%2];" \
                 : "=r"((r)[0]), "=r"((r)[1]) : "r"(addr))
#define CPA16(dst, src) \
    asm volatile("cp.async.cg.shared.global [%0], [%1], 16;" :: "r"(dst), "l"(src) : "memory")

__global__ void init_k() {
    if (threadIdx.x < NH) g_sum[threadIdx.x] = 0.0f;
}

// Elementwise tf32 pre-round of weights
__global__ __launch_bounds__(256) void round_k(const float* __restrict__ s,
                                               float* __restrict__ d, int n4) {
    int i = blockIdx.x * blockDim.x + threadIdx.x;
    if (i < n4) {
        float4 v = ((const float4*)s)[i];
        v.x = tf32r(v.x); v.y = tf32r(v.y); v.z = tf32r(v.z); v.w = tf32r(v.w);
        ((float4*)d)[i] = v;
    }
}

// x[n][c][l] -> xt[n][l][c], pre-rounded to tf32
__global__ __launch_bounds__(256) void transpose_k(const float* __restrict__ x,
                                                   float* __restrict__ xt) {
    __shared__ float t[32][33];
    const int n = blockIdx.z, c0 = blockIdx.y * 32, l0 = blockIdx.x * 32;
    const int tx = threadIdx.x, ty = threadIdx.y;
    const float* xp = x + ((size_t)n * CIN + c0) * L + l0;
    #pragma unroll
    for (int i = 0; i < 4; i++) t[ty + i * 8][tx] = xp[(size_t)(ty + i * 8) * L + tx];
    __syncthreads();
    float* xo = xt + ((size_t)n * L + l0) * CIN + c0;
    #pragma unroll
    for (int i = 0; i < 4; i++)
        xo[(size_t)(ty + i * 8) * CIN + tx] = tf32r(t[tx][ty + i * 8]);
}

// ---------------------------------------------------------------------------
// tf32 mma.sync GEMM: C[128x128] = A[128xK] * B[128xK]^T (both K-major,
// operands already tf32-rounded). CTA 128x128x32, 8 warps (2x4), warp 64x32.
// Fragments via ldmatrix.b16 (tf32 pair trick); no in-loop cvt.
// ---------------------------------------------------------------------------
template<int ID>
__global__ __launch_bounds__(256) void gemm_tc(
    const float* __restrict__ A0, const float* __restrict__ B0,
    float* __restrict__ C0, const float* __restrict__ bias)
{
    extern __shared__ float smemf[];
    const unsigned sb = s2u(smemf);
    const int tid = threadIdx.x, wid = tid >> 5, lid = tid & 31;
    const int gid = lid >> 2, tig = lid & 3;
    const int wm = wid & 1, wn = wid >> 1;
    const int bx = blockIdx.x, by = blockIdx.y, z = blockIdx.z;

    const float *A, *B;
    float* C;
    int lda, ldb, ldc, K;
    const float* biN = nullptr;
    const float* biM = nullptr;

    if constexpr (ID == 0) {
        const int o0 = (bx >> 2) * 768 + (bx & 3) * 128;
        A = A0 + (size_t)z * L * CIN + (size_t)by * 128 * CIN; lda = CIN;
        B = B0 + (size_t)o0 * CIN; ldb = CIN;
        C = C0 + (size_t)z * L * O3 + (size_t)by * 128 * O3 + o0; ldc = O3;
        biN = bias + o0; K = CIN;
    } else if constexpr (ID == 1) {
        const int o0 = (by >> 1) * 768 + 512 + (by & 1) * 128;
        A = A0 + (size_t)o0 * CIN; lda = CIN;
        B = B0 + (size_t)z * L * CIN + (size_t)bx * 128 * CIN; ldb = CIN;
        C = C0 + (size_t)z * ATTD * L +
            (size_t)((by >> 1) * 256 + (by & 1) * 128) * L + bx * 128; ldc = L;
        biM = bias + o0; K = CIN;
    } else if constexpr (ID == 2) {
        const float* base = A0 + (size_t)(z >> 3) * L * O3 + (z & 7) * 768;
        A = base + 256 + (size_t)by * 128 * O3; lda = O3;
        B = base + (size_t)bx * 128 * O3; ldb = O3;
        C = C0 + (size_t)z * L * L + (size_t)by * 128 * L + bx * 128; ldc = L;
        K = CIN;
    } else if constexpr (ID == 3) {
        A = A0 + (size_t)z * L * L + (size_t)by * 128 * L; lda = L;
        B = B0 + (size_t)(z >> 3) * ATTD * L +
            (size_t)((z & 7) * 256 + bx * 128) * L; ldb = L;
        C = C0 + (size_t)(z >> 3) * L * ATTD + (size_t)by * 128 * ATTD +
            (z & 7) * 256 + bx * 128; ldc = ATTD;
        K = L;
    } else {
        A = A0 + (size_t)by * 128 * ATTD; lda = ATTD;
        B = B0 + (size_t)z * L * ATTD + (size_t)bx * 128 * ATTD; ldb = ATTD;
        C = C0 + (size_t)z * CIN * L + (size_t)by * 128 * L + bx * 128; ldc = L;
        biM = bias + by * 128; K = ATTD;
    }

    float acc[4][4][4];
    #pragma unroll
    for (int mt = 0; mt < 4; mt++)
        #pragma unroll
        for (int nt = 0; nt < 4; nt++)
            #pragma unroll
            for (int r = 0; r < 4; r++) acc[mt][nt][r] = 0.0f;

    // ldmatrix row bases (buffer 0) and per-ks swizzled 16B offsets
    const int r7 = lid & 7;
    const int matA = lid >> 3;           // x4: 0..3
    const int matB = (lid >> 3) & 1;     // x2: 0..1
    unsigned rbA[4], rbB[4], offA[4], offB[4];
    #pragma unroll
    for (int mt = 0; mt < 4; mt++)
        rbA[mt] = sb + (unsigned)((wm * 64 + mt * 16 + (matA & 1) * 8 + r7) * 128);
    #pragma unroll
    for (int nt = 0; nt < 4; nt++)
        rbB[nt] = sb + 16384u + (unsigned)((wn * 32 + nt * 8 + r7) * 128);
    #pragma unroll
    for (int ks = 0; ks < 4; ks++) {
        offA[ks] = (unsigned)(((2 * ks + (matA >> 1)) ^ r7) << 4);
        offB[ks] = (unsigned)(((2 * ks + matB) ^ r7) << 4);
    }

    auto load_chunk = [&](int kc, int buf) {
        const float* ak = A + kc * 32;
        const float* bk = B + kc * 32;
        const unsigned sA = sb + buf * 32768u;
        const unsigned sB = sA + 16384u;
        #pragma unroll
        for (int i = 0; i < 4; i++) {
            const int idx = tid + i * 256, r = idx >> 3, c4 = idx & 7;
            const unsigned so = (unsigned)(r * 128 + ((c4 ^ (r & 7)) << 4));
            CPA16(sA + so, ak + (size_t)r * lda + c4 * 4);
        }
        #pragma unroll
        for (int i = 0; i < 4; i++) {
            const int idx = tid + i * 256, r = idx >> 3, c4 = idx & 7;
            const unsigned so = (unsigned)(r * 128 + ((c4 ^ (r & 7)) << 4));
            CPA16(sB + so, bk + (size_t)r * ldb + c4 * 4);
        }
        asm volatile("cp.async.commit_group;" ::: "memory");
    };

    const int NC = K >> 5;
    load_chunk(0, 0);

    for (int c = 0; c < NC; c++) {
        const int buf = c & 1;
        if (c + 1 < NC) {
            load_chunk(c + 1, buf ^ 1);
            asm volatile("cp.async.wait_group 1;" ::: "memory");
        } else {
            asm volatile("cp.async.wait_group 0;" ::: "memory");
        }
        __syncthreads();

        const unsigned bo = buf * 32768u;
        #pragma unroll
        for (int ks = 0; ks < 4; ks++) {
            unsigned af[4][4], bf[4][2];
            #pragma unroll
            for (int mt = 0; mt < 4; mt++) LDSM4(af[mt], rbA[mt] + bo + offA[ks]);
            #pragma unroll
            for (int nt = 0; nt < 4; nt++) LDSM2(bf[nt], rbB[nt] + bo + offB[ks]);
            #pragma unroll
            for (int mt = 0; mt < 4; mt++)
                #pragma unroll
                for (int nt = 0; nt < 4; nt++)
                    mma8(acc[mt][nt], af[mt], bf[nt]);
        }
        __syncthreads();
    }

    // Epilogue: thread owns rows wm*64+mt*16+gid(+8), cols wn*32+nt*8+tig*2(+1)
    float vinv = 1.0f, lsum = 0.0f;
    if constexpr (ID == 3) vinv = 1.0f / g_sum[z];

    #pragma unroll
    for (int mt = 0; mt < 4; mt++) {
        const int r0 = wm * 64 + mt * 16 + gid;
        float bm0 = 0.0f, bm1 = 0.0f;
        if constexpr (ID == 1 || ID == 4) { bm0 = biM[r0]; bm1 = biM[r0 + 8]; }
        #pragma unroll
        for (int nt = 0; nt < 4; nt++) {
            const int cn = wn * 32 + nt * 8 + tig * 2;
            float v0 = acc[mt][nt][0], v1 = acc[mt][nt][1];
            float v2 = acc[mt][nt][2], v3 = acc[mt][nt][3];
            if constexpr (ID == 0) {
                const float2 bv = *(const float2*)(biN + cn);
                v0 = tf32r((v0 + bv.x) * SC); v1 = tf32r((v1 + bv.y) * SC);
                v2 = tf32r((v2 + bv.x) * SC); v3 = tf32r((v3 + bv.y) * SC);
            } else if constexpr (ID == 1) {
                v0 = tf32r((v0 + bm0) * SC); v1 = tf32r((v1 + bm0) * SC);
                v2 = tf32r((v2 + bm1) * SC); v3 = tf32r((v3 + bm1) * SC);
            } else if constexpr (ID == 2) {
                v0 = __expf(v0); v1 = __expf(v1);
                v2 = __expf(v2); v3 = __expf(v3);
                lsum += (v0 + v1) + (v2 + v3);
                v0 = tf32r(v0); v1 = tf32r(v1); v2 = tf32r(v2); v3 = tf32r(v3);
            } else if constexpr (ID == 3) {
                v0 = tf32r(v0 * vinv); v1 = tf32r(v1 * vinv);
                v2 = tf32r(v2 * vinv); v3 = tf32r(v3 * vinv);
            } else {
                v0 += bm0; v1 += bm0; v2 += bm1; v3 += bm1;
            }
            *(float2*)(C + (size_t)r0 * ldc + cn)       = make_float2(v0, v1);
            *(float2*)(C + (size_t)(r0 + 8) * ldc + cn) = make_float2(v2, v3);
        }
    }

    if constexpr (ID == 2) {
        __syncthreads();
        smemf[tid] = lsum;
        __syncthreads();
        for (int s = 128; s > 0; s >>= 1) {
            if (tid < s) smemf[tid] += smemf[tid + s];
            __syncthreads();
        }
        if (tid == 0) atomicAdd(&g_sum[z], smemf[0]);
    }
}

// ---------------------------------------------------------------------------
extern "C" void kernel_launch(void* const* d_in, const int* in_sizes, int n_in,
                              void* d_out, int out_size)
{
    const float *x = nullptr, *w_in = nullptr, *b_in = nullptr;
    const float *w_out = nullptr, *b_out = nullptr;
    for (int i = 0; i < n_in; i++) {
        const float* p = (const float*)d_in[i];
        switch (in_sizes[i]) {
            case NB * CIN * L:  x     = p; break;
            case O3 * CIN:      w_in  = p; break;
            case O3:            b_in  = p; break;
            case CIN * ATTD:    w_out = p; break;
            case CIN:           b_out = p; break;
            default: break;
        }
    }
    float* out = (float*)d_out;

    void* p;
    cudaGetSymbolAddress(&p, g_xt);   float* XT = (float*)p;
    cudaGetSymbolAddress(&p, g_st);   float* ST = (float*)p;
    cudaGetSymbolAddress(&p, g_v);    float* V  = (float*)p;
    cudaGetSymbolAddress(&p, g_p);    float* P  = (float*)p;
    cudaGetSymbolAddress(&p, g_ot);   float* OT = (float*)p;
    cudaGetSymbolAddress(&p, g_win);  float* WI = (float*)p;
    cudaGetSymbolAddress(&p, g_wout); float* WO = (float*)p;

    cudaFuncSetAttribute(gemm_tc<0>, cudaFuncAttributeMaxDynamicSharedMemorySize, SMEM_BYTES);
    cudaFuncSetAttribute(gemm_tc<1>, cudaFuncAttributeMaxDynamicSharedMemorySize, SMEM_BYTES);
    cudaFuncSetAttribute(gemm_tc<2>, cudaFuncAttributeMaxDynamicSharedMemorySize, SMEM_BYTES);
    cudaFuncSetAttribute(gemm_tc<3>, cudaFuncAttributeMaxDynamicSharedMemorySize, SMEM_BYTES);
    cudaFuncSetAttribute(gemm_tc<4>, cudaFuncAttributeMaxDynamicSharedMemorySize, SMEM_BYTES);

    init_k<<<1, 64>>>();
    round_k<<<(O3 * CIN / 4 + 255) / 256, 256>>>(w_in, WI, O3 * CIN / 4);
    round_k<<<(CIN * ATTD / 4 + 255) / 256, 256>>>(w_out, WO, CIN * ATTD / 4);
    transpose_k<<<dim3(32, 8, 8), dim3(32, 8)>>>(x, XT);
    // K1a: S_T (q,k slices)
    gemm_tc<0><<<dim3(32, 8, 8), 256, SMEM_BYTES>>>(XT, WI, ST, b_in);
    // K1b: V
    gemm_tc<1><<<dim3(8, 16, 8), 256, SMEM_BYTES>>>(WI, XT, V, b_in);
    // K2: Pm = exp(K_T Q_T^T), per-head sums
    gemm_tc<2><<<dim3(8, 8, 64), 256, SMEM_BYTES>>>(ST, ST, P, nullptr);
    // K4: O_T = (Pm V^T) / sum
    gemm_tc<3><<<dim3(2, 8, 64), 256, SMEM_BYTES>>>(P, V, OT, nullptr);
    // K5: out = w_out O_T^T + b_out
    gemm_tc<4><<<dim3(8, 2, 8), 256, SMEM_BYTES>>>(WO, OT, out, b_out);
}

// round 5
// speedup vs baseline: 7.6456x; 2.5816x over previous
#include <cuda_runtime.h>
#include <cuda_bf16.h>
#include <cstdint>

static constexpr int L = 1024, CIN = 256, O3 = 6144, ATTD = 2048, NB = 8, NH = 64;
static constexpr float SC = 5.0f / 48.0f;
static constexpr unsigned SMEM_BYTES = 2 * (16384 + 16384);   // 2 stages x (A+B)

// Scratch (device globals per allocation-free rule) — all GEMM operands bf16
__device__ __nv_bfloat16 g_xt[(size_t)NB * L * CIN];
__device__ __nv_bfloat16 g_st[(size_t)NB * L * O3];
__device__ __nv_bfloat16 g_v [(size_t)NB * ATTD * L];
__device__ __nv_bfloat16 g_p [(size_t)NH * L * L];
__device__ __nv_bfloat16 g_ot[(size_t)NB * L * ATTD];
__device__ __nv_bfloat16 g_win[(size_t)O3 * CIN];
__device__ __nv_bfloat16 g_wout[(size_t)CIN * ATTD];
__device__ float g_sum[NH];

// ---------------------------------------------------------------------------
__device__ __forceinline__ unsigned s2u(const void* p) {
    unsigned a;
    asm("{ .reg .u64 t; cvta.to.shared.u64 t, %1; cvt.u32.u64 %0, t; }"
        : "=r"(a) : "l"(p));
    return a;
}
__device__ __forceinline__ void mma16(float* d, const unsigned* a, const unsigned* b) {
    asm volatile(
        "mma.sync.aligned.m16n8k16.row.col.f32.bf16.bf16.f32 "
        "{%0,%1,%2,%3}, {%4,%5,%6,%7}, {%8,%9}, {%0,%1,%2,%3};"
        : "+f"(d[0]), "+f"(d[1]), "+f"(d[2]), "+f"(d[3])
        : "r"(a[0]), "r"(a[1]), "r"(a[2]), "r"(a[3]), "r"(b[0]), "r"(b[1]));
}
#define LDSM4(r, addr) \
    asm volatile("ldmatrix.sync.aligned.m8n8.x4.shared.b16 {%0,%1,%2,%3}, [%4];" \
                 : "=r"((r)[0]), "=r"((r)[1]), "=r"((r)[2]), "=r"((r)[3]) : "r"(addr))
#define LDSM2(r, addr) \
    asm volatile("ldmatrix.sync.aligned.m8n8.x2.shared.b16 {%0,%1}, [%2];" \
                 : "=r"((r)[0]), "=r"((r)[1]) : "r"(addr))
#define CPA16(dst, src) \
    asm volatile("cp.async.cg.shared.global [%0], [%1], 16;" :: "r"(dst), "l"(src) : "memory")

__global__ void init_k() {
    if (threadIdx.x < NH) g_sum[threadIdx.x] = 0.0f;
}

// fp32 weights -> bf16
__global__ __launch_bounds__(256) void round_k(const float* __restrict__ s,
                                               __nv_bfloat16* __restrict__ d, int n4) {
    int i = blockIdx.x * blockDim.x + threadIdx.x;
    if (i < n4) {
        float4 v = ((const float4*)s)[i];
        __nv_bfloat162 h0 = __floats2bfloat162_rn(v.x, v.y);
        __nv_bfloat162 h1 = __floats2bfloat162_rn(v.z, v.w);
        ((__nv_bfloat162*)d)[2 * i]     = h0;
        ((__nv_bfloat162*)d)[2 * i + 1] = h1;
    }
}

// x[n][c][l] (fp32) -> xt[n][l][c] (bf16)
__global__ __launch_bounds__(256) void transpose_k(const float* __restrict__ x,
                                                   __nv_bfloat16* __restrict__ xt) {
    __shared__ float t[32][33];
    const int n = blockIdx.z, c0 = blockIdx.y * 32, l0 = blockIdx.x * 32;
    const int tx = threadIdx.x, ty = threadIdx.y;
    const int tl = ty * 32 + tx;
    const float* xp = x + ((size_t)n * CIN + c0) * L + l0;
    #pragma unroll
    for (int i = 0; i < 4; i++) t[ty + i * 8][tx] = xp[(size_t)(ty + i * 8) * L + tx];
    __syncthreads();
    __nv_bfloat16* xo = xt + ((size_t)n * L + l0) * CIN + c0;
    #pragma unroll
    for (int i = 0; i < 2; i++) {
        const int p = tl + i * 256;        // 512 bf16x2 pairs per tile
        const int li = p >> 4, cp = p & 15;
        __nv_bfloat162 h = __floats2bfloat162_rn(t[2 * cp][li], t[2 * cp + 1][li]);
        *(__nv_bfloat162*)(xo + (size_t)li * CIN + 2 * cp) = h;
    }
}

// ---------------------------------------------------------------------------
// bf16 mma.sync GEMM: C[128x128] = A[128xK] * B[128xK]^T (both K-major bf16).
// CTA 128x128x64, 8 warps (2x4), warp tile 64x32, mma m16n8k16, fp32 accum.
// ID 0: S_T(q,k) = XT * w_in^T,  epi (acc + b_in[col]) * SC   -> bf16
// ID 1: V        = w_in * XT^T,  epi (acc + b_in[row]) * SC   -> bf16
// ID 2: Pm       = K_T * Q_T^T,  epi exp(acc), sum -> g_sum   -> bf16
// ID 3: O_T      = Pm * V^T,     epi acc / g_sum[z]           -> bf16
// ID 4: out      = w_out * O_T^T,epi acc + b_out[row]         -> fp32
// ---------------------------------------------------------------------------
template<int ID>
__global__ __launch_bounds__(256) void gemm_tc(
    const __nv_bfloat16* __restrict__ A0, const __nv_bfloat16* __restrict__ B0,
    void* __restrict__ C0, const float* __restrict__ bias)
{
    extern __shared__ float smemf[];
    const unsigned sb = s2u(smemf);
    const int tid = threadIdx.x, wid = tid >> 5, lid = tid & 31;
    const int gid = lid >> 2, tig = lid & 3;
    const int wm = wid & 1, wn = wid >> 1;
    const int bx = blockIdx.x, by = blockIdx.y, z = blockIdx.z;

    const __nv_bfloat16 *A, *B;
    __nv_bfloat16* Cb = nullptr;
    float* Cf = nullptr;
    int lda, ldb, ldc, K;
    const float* biN = nullptr;
    const float* biM = nullptr;

    if constexpr (ID == 0) {
        const int o0 = (bx >> 2) * 768 + (bx & 3) * 128;
        A = A0 + (size_t)z * L * CIN + (size_t)by * 128 * CIN; lda = CIN;
        B = B0 + (size_t)o0 * CIN; ldb = CIN;
        Cb = (__nv_bfloat16*)C0 + (size_t)z * L * O3 + (size_t)by * 128 * O3 + o0;
        ldc = O3; biN = bias + o0; K = CIN;
    } else if constexpr (ID == 1) {
        const int o0 = (by >> 1) * 768 + 512 + (by & 1) * 128;
        A = A0 + (size_t)o0 * CIN; lda = CIN;
        B = B0 + (size_t)z * L * CIN + (size_t)bx * 128 * CIN; ldb = CIN;
        Cb = (__nv_bfloat16*)C0 + (size_t)z * ATTD * L +
             (size_t)((by >> 1) * 256 + (by & 1) * 128) * L + bx * 128;
        ldc = L; biM = bias + o0; K = CIN;
    } else if constexpr (ID == 2) {
        const __nv_bfloat16* base = A0 + (size_t)(z >> 3) * L * O3 + (z & 7) * 768;
        A = base + 256 + (size_t)by * 128 * O3; lda = O3;
        B = base + (size_t)bx * 128 * O3; ldb = O3;
        Cb = (__nv_bfloat16*)C0 + (size_t)z * L * L + (size_t)by * 128 * L + bx * 128;
        ldc = L; K = CIN;
    } else if constexpr (ID == 3) {
        A = A0 + (size_t)z * L * L + (size_t)by * 128 * L; lda = L;
        B = B0 + (size_t)(z >> 3) * ATTD * L +
            (size_t)((z & 7) * 256 + bx * 128) * L; ldb = L;
        Cb = (__nv_bfloat16*)C0 + (size_t)(z >> 3) * L * ATTD +
             (size_t)by * 128 * ATTD + (z & 7) * 256 + bx * 128;
        ldc = ATTD; K = L;
    } else {
        A = A0 + (size_t)by * 128 * ATTD; lda = ATTD;
        B = B0 + (size_t)z * L * ATTD + (size_t)bx * 128 * ATTD; ldb = ATTD;
        Cf = (float*)C0 + (size_t)z * CIN * L + (size_t)by * 128 * L + bx * 128;
        ldc = L; biM = bias + by * 128; K = ATTD;
    }

    float acc[4][4][4];
    #pragma unroll
    for (int mt = 0; mt < 4; mt++)
        #pragma unroll
        for (int nt = 0; nt < 4; nt++)
            #pragma unroll
            for (int r = 0; r < 4; r++) acc[mt][nt][r] = 0.0f;

    // ldmatrix bases: rows are 128B (= 64 bf16); swizzle identical to tf32 case
    const int r7 = lid & 7;
    const int matA = lid >> 3;
    const int matB = (lid >> 3) & 1;
    unsigned rbA[4], rbB[4], offA[4], offB[4];
    #pragma unroll
    for (int mt = 0; mt < 4; mt++)
        rbA[mt] = sb + (unsigned)((wm * 64 + mt * 16 + (matA & 1) * 8 + r7) * 128);
    #pragma unroll
    for (int nt = 0; nt < 4; nt++)
        rbB[nt] = sb + 16384u + (unsigned)((wn * 32 + nt * 8 + r7) * 128);
    #pragma unroll
    for (int ks = 0; ks < 4; ks++) {
        offA[ks] = (unsigned)(((2 * ks + (matA >> 1)) ^ r7) << 4);
        offB[ks] = (unsigned)(((2 * ks + matB) ^ r7) << 4);
    }

    // 128 rows x 64 bf16 (128B) per tile, XOR-swizzled at 16B granularity
    auto load_chunk = [&](int kc, int buf) {
        const __nv_bfloat16* ak = A + kc * 64;
        const __nv_bfloat16* bk = B + kc * 64;
        const unsigned sA = sb + buf * 32768u;
        const unsigned sB = sA + 16384u;
        #pragma unroll
        for (int i = 0; i < 4; i++) {
            const int idx = tid + i * 256, r = idx >> 3, c4 = idx & 7;
            const unsigned so = (unsigned)(r * 128 + ((c4 ^ (r & 7)) << 4));
            CPA16(sA + so, ak + (size_t)r * lda + c4 * 8);
        }
        #pragma unroll
        for (int i = 0; i < 4; i++) {
            const int idx = tid + i * 256, r = idx >> 3, c4 = idx & 7;
            const unsigned so = (unsigned)(r * 128 + ((c4 ^ (r & 7)) << 4));
            CPA16(sB + so, bk + (size_t)r * ldb + c4 * 8);
        }
        asm volatile("cp.async.commit_group;" ::: "memory");
    };

    const int NC = K >> 6;    // K-chunks of 64
    load_chunk(0, 0);

    for (int c = 0; c < NC; c++) {
        const int buf = c & 1;
        if (c + 1 < NC) {
            load_chunk(c + 1, buf ^ 1);
            asm volatile("cp.async.wait_group 1;" ::: "memory");
        } else {
            asm volatile("cp.async.wait_group 0;" ::: "memory");
        }
        __syncthreads();

        const unsigned bo = buf * 32768u;
        #pragma unroll
        for (int ks = 0; ks < 4; ks++) {
            unsigned af[4][4], bf[4][2];
            #pragma unroll
            for (int mt = 0; mt < 4; mt++) LDSM4(af[mt], rbA[mt] + bo + offA[ks]);
            #pragma unroll
            for (int nt = 0; nt < 4; nt++) LDSM2(bf[nt], rbB[nt] + bo + offB[ks]);
            #pragma unroll
            for (int mt = 0; mt < 4; mt++)
                #pragma unroll
                for (int nt = 0; nt < 4; nt++)
                    mma16(acc[mt][nt], af[mt], bf[nt]);
        }
        __syncthreads();
    }

    // Epilogue: thread owns rows wm*64+mt*16+gid(+8), cols wn*32+nt*8+tig*2(+1)
    float vinv = 1.0f, lsum = 0.0f;
    if constexpr (ID == 3) vinv = 1.0f / g_sum[z];

    #pragma unroll
    for (int mt = 0; mt < 4; mt++) {
        const int r0 = wm * 64 + mt * 16 + gid;
        float bm0 = 0.0f, bm1 = 0.0f;
        if constexpr (ID == 1 || ID == 4) { bm0 = biM[r0]; bm1 = biM[r0 + 8]; }
        #pragma unroll
        for (int nt = 0; nt < 4; nt++) {
            const int cn = wn * 32 + nt * 8 + tig * 2;
            float v0 = acc[mt][nt][0], v1 = acc[mt][nt][1];
            float v2 = acc[mt][nt][2], v3 = acc[mt][nt][3];
            if constexpr (ID == 0) {
                const float2 bv = *(const float2*)(biN + cn);
                v0 = (v0 + bv.x) * SC; v1 = (v1 + bv.y) * SC;
                v2 = (v2 + bv.x) * SC; v3 = (v3 + bv.y) * SC;
            } else if constexpr (ID == 1) {
                v0 = (v0 + bm0) * SC; v1 = (v1 + bm0) * SC;
                v2 = (v2 + bm1) * SC; v3 = (v3 + bm1) * SC;
            } else if constexpr (ID == 2) {
                v0 = __expf(v0); v1 = __expf(v1);
                v2 = __expf(v2); v3 = __expf(v3);
                lsum += (v0 + v1) + (v2 + v3);
            } else if constexpr (ID == 3) {
                v0 *= vinv; v1 *= vinv; v2 *= vinv; v3 *= vinv;
            } else {
                v0 += bm0; v1 += bm0; v2 += bm1; v3 += bm1;
            }
            if constexpr (ID == 4) {
                *(float2*)(Cf + (size_t)r0 * ldc + cn)       = make_float2(v0, v1);
                *(float2*)(Cf + (size_t)(r0 + 8) * ldc + cn) = make_float2(v2, v3);
            } else {
                *(__nv_bfloat162*)(Cb + (size_t)r0 * ldc + cn) =
                    __floats2bfloat162_rn(v0, v1);
                *(__nv_bfloat162*)(Cb + (size_t)(r0 + 8) * ldc + cn) =
                    __floats2bfloat162_rn(v2, v3);
            }
        }
    }

    if constexpr (ID == 2) {
        __syncthreads();
        smemf[tid] = lsum;
        __syncthreads();
        for (int s = 128; s > 0; s >>= 1) {
            if (tid < s) smemf[tid] += smemf[tid + s];
            __syncthreads();
        }
        if (tid == 0) atomicAdd(&g_sum[z], smemf[0]);
    }
}

// ---------------------------------------------------------------------------
extern "C" void kernel_launch(void* const* d_in, const int* in_sizes, int n_in,
                              void* d_out, int out_size)
{
    const float *x = nullptr, *w_in = nullptr, *b_in = nullptr;
    const float *w_out = nullptr, *b_out = nullptr;
    for (int i = 0; i < n_in; i++) {
        const float* p = (const float*)d_in[i];
        switch (in_sizes[i]) {
            case NB * CIN * L:  x     = p; break;
            case O3 * CIN:      w_in  = p; break;
            case O3:            b_in  = p; break;
            case CIN * ATTD:    w_out = p; break;
            case CIN:           b_out = p; break;
            default: break;
        }
    }
    float* out = (float*)d_out;

    void* p;
    cudaGetSymbolAddress(&p, g_xt);   __nv_bfloat16* XT = (__nv_bfloat16*)p;
    cudaGetSymbolAddress(&p, g_st);   __nv_bfloat16* ST = (__nv_bfloat16*)p;
    cudaGetSymbolAddress(&p, g_v);    __nv_bfloat16* V  = (__nv_bfloat16*)p;
    cudaGetSymbolAddress(&p, g_p);    __nv_bfloat16* P  = (__nv_bfloat16*)p;
    cudaGetSymbolAddress(&p, g_ot);   __nv_bfloat16* OT = (__nv_bfloat16*)p;
    cudaGetSymbolAddress(&p, g_win);  __nv_bfloat16* WI = (__nv_bfloat16*)p;
    cudaGetSymbolAddress(&p, g_wout); __nv_bfloat16* WO = (__nv_bfloat16*)p;

    cudaFuncSetAttribute(gemm_tc<0>, cudaFuncAttributeMaxDynamicSharedMemorySize, SMEM_BYTES);
    cudaFuncSetAttribute(gemm_tc<1>, cudaFuncAttributeMaxDynamicSharedMemorySize, SMEM_BYTES);
    cudaFuncSetAttribute(gemm_tc<2>, cudaFuncAttributeMaxDynamicSharedMemorySize, SMEM_BYTES);
    cudaFuncSetAttribute(gemm_tc<3>, cudaFuncAttributeMaxDynamicSharedMemorySize, SMEM_BYTES);
    cudaFuncSetAttribute(gemm_tc<4>, cudaFuncAttributeMaxDynamicSharedMemorySize, SMEM_BYTES);

    init_k<<<1, 64>>>();
    round_k<<<(O3 * CIN / 4 + 255) / 256, 256>>>(w_in, WI, O3 * CIN / 4);
    round_k<<<(CIN * ATTD / 4 + 255) / 256, 256>>>(w_out, WO, CIN * ATTD / 4);
    transpose_k<<<dim3(32, 8, 8), dim3(32, 8)>>>(x, XT);
    // K1a: S_T (q,k slices)
    gemm_tc<0><<<dim3(32, 8, 8), 256, SMEM_BYTES>>>(XT, WI, ST, b_in);
    // K1b: V
    gemm_tc<1><<<dim3(8, 16, 8), 256, SMEM_BYTES>>>(WI, XT, V, b_in);
    // K2: Pm = exp(K_T Q_T^T), per-head sums
    gemm_tc<2><<<dim3(8, 8, 64), 256, SMEM_BYTES>>>(ST, ST, P, nullptr);
    // K4: O_T = (Pm V^T) / sum
    gemm_tc<3><<<dim3(2, 8, 64), 256, SMEM_BYTES>>>(P, V, OT, nullptr);
    // K5: out = w_out O_T^T + b_out
    gemm_tc<4><<<dim3(8, 2, 8), 256, SMEM_BYTES>>>(WO, OT, out, b_out);
}